// round 2
// baseline (speedup 1.0000x reference)
#include <cuda_runtime.h>
#include <math.h>

#define NN   256
#define CIN  128
#define HH   4
#define DD   32
#define NPOS (NN*NN)

// ---------------- scratch (device globals; no runtime allocation) ----------------
__device__ float g_Wt[CIN][520];          // [c][e]: e<128 wq*scale, <256 wk, <384 wv, <512 wg, <516 wb
__device__ float g_Wot[CIN][CIN];         // [e][c] = w_o[c][e]
__device__ float g_q[NN][HH][NN][DD];
__device__ float g_k[NN][HH][NN][DD];
__device__ float g_v[NN][HH][NN][DD];
__device__ float g_gate[(size_t)NPOS*CIN];
__device__ float g_tb[HH][NN][NN];        // [h][key j][query i]
__device__ float g_o[(size_t)NPOS*CIN];   // gated attention output [i][j][h*32+d]

// ---------------- weight prep: transpose + concat + bake q scale ----------------
__global__ void prep_kernel(const float* __restrict__ wb, const float* __restrict__ wq,
                            const float* __restrict__ wk, const float* __restrict__ wv,
                            const float* __restrict__ wg, const float* __restrict__ wo) {
    int idx = blockIdx.x * blockDim.x + threadIdx.x;
    if (idx < CIN * 520) {
        int c = idx / 520, e = idx % 520;
        float val = 0.f;
        if      (e < 128) val = wq[e * CIN + c] * 0.17677669529663687f;   // 1/sqrt(32)
        else if (e < 256) val = wk[(e - 128) * CIN + c];
        else if (e < 384) val = wv[(e - 256) * CIN + c];
        else if (e < 512) val = wg[(e - 384) * CIN + c];
        else if (e < 516) val = wb[(e - 512) * CIN + c];
        g_Wt[c][e] = val;
    }
    if (idx < CIN * CIN) {
        int e = idx / CIN, c = idx % CIN;
        g_Wot[e][c] = wo[c * CIN + e];
    }
}

// ---------------- fused LayerNorm + {q,k,v,gate,tri-bias} projection ----------------
__global__ __launch_bounds__(256) void lnproj_kernel(const float* __restrict__ x,
                                                     const float* __restrict__ lnw,
                                                     const float* __restrict__ lnb,
                                                     const float* __restrict__ bg) {
    __shared__ float xs[64][132];    // normalized activations, row-major, padded
    __shared__ float Bs[32][68];     // weight K-chunk
    __shared__ float mu_s[64], rs_s[64];

    int t = threadIdx.x;
    int p0 = blockIdx.x * 64;
    int lane = t & 31, w = t >> 5;

    // per-row LN stats: warp w handles rows 8w..8w+7
    for (int rr = 0; rr < 8; rr++) {
        int r = w * 8 + rr;
        const float* xp = x + (size_t)(p0 + r) * CIN;
        float v0 = xp[lane], v1 = xp[lane + 32], v2 = xp[lane + 64], v3 = xp[lane + 96];
        float s = v0 + v1 + v2 + v3;
        float q = v0 * v0 + v1 * v1 + v2 * v2 + v3 * v3;
        #pragma unroll
        for (int off = 16; off; off >>= 1) {
            s += __shfl_down_sync(0xffffffffu, s, off);
            q += __shfl_down_sync(0xffffffffu, q, off);
        }
        if (lane == 0) {
            float m = s * (1.f / 128.f);
            mu_s[r] = m;
            rs_s[r] = rsqrtf(q * (1.f / 128.f) - m * m + 1e-5f);
        }
    }
    __syncthreads();

    // normalize into smem
    for (int l = t * 4; l < 64 * 128; l += 1024) {
        int r = l >> 7, c = l & 127;
        float4 xv = *(const float4*)(x + (size_t)(p0 + r) * CIN + c);
        float m = mu_s[r], rs = rs_s[r];
        float4 o;
        o.x = (xv.x - m) * rs * lnw[c + 0] + lnb[c + 0];
        o.y = (xv.y - m) * rs * lnw[c + 1] + lnb[c + 1];
        o.z = (xv.z - m) * rs * lnw[c + 2] + lnb[c + 2];
        o.w = (xv.w - m) * rs * lnw[c + 3] + lnb[c + 3];
        *(float4*)&xs[r][c] = o;
    }
    __syncthreads();

    int tx = t & 15, ty = t >> 4;

    // main GEMM: [64 pos] x [512 out], K=128, 8 N-chunks of 64
    for (int nc = 0; nc < 8; nc++) {
        float acc[4][4] = {};
        int nbase = nc * 64;
        for (int kc = 0; kc < 4; kc++) {
            __syncthreads();
            for (int f = t; f < 512; f += 256) {
                int kk = f >> 4, c4 = (f & 15) * 4;
                *(float4*)&Bs[kk][c4] = *(const float4*)&g_Wt[kc * 32 + kk][nbase + c4];
            }
            __syncthreads();
            #pragma unroll
            for (int kk = 0; kk < 32; kk++) {
                int k = kc * 32 + kk;
                float a0 = xs[ty * 4 + 0][k];
                float a1 = xs[ty * 4 + 1][k];
                float a2 = xs[ty * 4 + 2][k];
                float a3 = xs[ty * 4 + 3][k];
                float4 b = *(const float4*)&Bs[kk][tx * 4];
                acc[0][0] += a0 * b.x; acc[0][1] += a0 * b.y; acc[0][2] += a0 * b.z; acc[0][3] += a0 * b.w;
                acc[1][0] += a1 * b.x; acc[1][1] += a1 * b.y; acc[1][2] += a1 * b.z; acc[1][3] += a1 * b.w;
                acc[2][0] += a2 * b.x; acc[2][1] += a2 * b.y; acc[2][2] += a2 * b.z; acc[2][3] += a2 * b.w;
                acc[3][0] += a3 * b.x; acc[3][1] += a3 * b.y; acc[3][2] += a3 * b.z; acc[3][3] += a3 * b.w;
            }
        }
        // store this N-chunk
        int e0  = nbase + tx * 4;
        int sel = e0 >> 7;        // 0=q 1=k 2=v 3=gate
        int loc = e0 & 127;
        int h   = loc >> 5, d0 = loc & 31;
        #pragma unroll
        for (int rr = 0; rr < 4; rr++) {
            int p  = p0 + ty * 4 + rr;
            int ii = p >> 8, jj = p & 255;
            float4 v = make_float4(acc[rr][0], acc[rr][1], acc[rr][2], acc[rr][3]);
            if      (sel == 0) *(float4*)&g_q[ii][h][jj][d0] = v;
            else if (sel == 1) *(float4*)&g_k[ii][h][jj][d0] = v;
            else if (sel == 2) *(float4*)&g_v[ii][h][jj][d0] = v;
            else {
                float4 bgv = *(const float4*)(bg + loc);
                float4 gv;
                gv.x = 1.f / (1.f + __expf(-(v.x + bgv.x)));
                gv.y = 1.f / (1.f + __expf(-(v.y + bgv.y)));
                gv.z = 1.f / (1.f + __expf(-(v.z + bgv.z)));
                gv.w = 1.f / (1.f + __expf(-(v.w + bgv.w)));
                *(float4*)(g_gate + (size_t)p * CIN + loc) = gv;
            }
        }
    }

    // triangle bias: thread -> (row, head)
    {
        int r = t >> 2, h = t & 3;
        float acc = 0.f;
        #pragma unroll 8
        for (int c = 0; c < 128; c++) acc += xs[r][c] * g_Wt[c][512 + h];
        int p = p0 + r;
        int ii = p >> 8, jj = p & 255;
        g_tb[h][jj][ii] = acc;   // [h][key][query]
    }
}

// ---------------- per-(row,head) flash attention + gating ----------------
__global__ __launch_bounds__(256) void attn_kernel(const float* __restrict__ mask) {
    __shared__ float ks[128][32];
    __shared__ float vs[128][32];
    __shared__ float mb[256];

    int i = blockIdx.x >> 2;
    int h = blockIdx.x & 3;
    int q = threadIdx.x;          // one query per thread

    mb[q] = 1e9f * (mask[i * NN + q] - 1.0f);

    float qv[32];
    {
        const float4* qp = (const float4*)&g_q[i][h][q][0];
        #pragma unroll
        for (int d4 = 0; d4 < 8; d4++) {
            float4 v = qp[d4];
            qv[d4 * 4 + 0] = v.x; qv[d4 * 4 + 1] = v.y;
            qv[d4 * 4 + 2] = v.z; qv[d4 * 4 + 3] = v.w;
        }
    }

    float acc[32];
    #pragma unroll
    for (int d = 0; d < 32; d++) acc[d] = 0.f;
    float m = -1e30f, l = 0.f;

    for (int kb = 0; kb < 2; kb++) {
        __syncthreads();
        {
            const float4* kp = (const float4*)&g_k[i][h][kb * 128][0];
            const float4* vp = (const float4*)&g_v[i][h][kb * 128][0];
            float4* ksd = (float4*)ks;
            float4* vsd = (float4*)vs;
            for (int f = q; f < 1024; f += 256) { ksd[f] = kp[f]; vsd[f] = vp[f]; }
        }
        __syncthreads();

        const float* tbp = &g_tb[h][kb * 128][0];
        float tb_c = tbp[q];
        for (int kk = 0; kk < 128; kk++) {
            float tb_n = (kk < 127) ? tbp[(kk + 1) * NN + q] : 0.f;
            float s = 0.f;
            const float4* kr = (const float4*)&ks[kk][0];
            #pragma unroll
            for (int d4 = 0; d4 < 8; d4++) {
                float4 kvv = kr[d4];
                s += qv[d4 * 4 + 0] * kvv.x + qv[d4 * 4 + 1] * kvv.y
                   + qv[d4 * 4 + 2] * kvv.z + qv[d4 * 4 + 3] * kvv.w;
            }
            s += mb[kb * 128 + kk] + tb_c;
            if (s > m) {                      // rare after warmup
                float corr = __expf(m - s);
                m = s;
                l *= corr;
                #pragma unroll
                for (int d = 0; d < 32; d++) acc[d] *= corr;
            }
            float p = __expf(s - m);
            l += p;
            const float4* vr = (const float4*)&vs[kk][0];
            #pragma unroll
            for (int d4 = 0; d4 < 8; d4++) {
                float4 vvv = vr[d4];
                acc[d4 * 4 + 0] += p * vvv.x; acc[d4 * 4 + 1] += p * vvv.y;
                acc[d4 * 4 + 2] += p * vvv.z; acc[d4 * 4 + 3] += p * vvv.w;
            }
            tb_c = tb_n;
        }
    }

    float rcp = 1.f / l;
    size_t pbase = ((size_t)(i * NN + q)) * CIN + h * DD;
    const float4* gp = (const float4*)(g_gate + pbase);
    float4* op = (float4*)(g_o + pbase);
    #pragma unroll
    for (int d4 = 0; d4 < 8; d4++) {
        float4 gv = gp[d4];
        float4 ov;
        ov.x = acc[d4 * 4 + 0] * rcp * gv.x;
        ov.y = acc[d4 * 4 + 1] * rcp * gv.y;
        ov.z = acc[d4 * 4 + 2] * rcp * gv.z;
        ov.w = acc[d4 * 4 + 3] * rcp * gv.w;
        op[d4] = ov;
    }
}

// ---------------- output projection: out = o_gated @ w_o^T + b_o ----------------
__global__ __launch_bounds__(256) void outproj_kernel(float* __restrict__ out,
                                                      const float* __restrict__ bo) {
    __shared__ float os[64][132];
    __shared__ float Bs[32][68];

    int t = threadIdx.x;
    int p0 = blockIdx.x * 64;

    for (int l = t * 4; l < 64 * 128; l += 1024) {
        int r = l >> 7, c = l & 127;
        *(float4*)&os[r][c] = *(const float4*)(g_o + (size_t)(p0 + r) * CIN + c);
    }
    __syncthreads();

    int tx = t & 15, ty = t >> 4;
    for (int nc = 0; nc < 2; nc++) {
        float acc[4][4] = {};
        int nbase = nc * 64;
        for (int kc = 0; kc < 4; kc++) {
            __syncthreads();
            for (int f = t; f < 512; f += 256) {
                int kk = f >> 4, c4 = (f & 15) * 4;
                *(float4*)&Bs[kk][c4] = *(const float4*)&g_Wot[kc * 32 + kk][nbase + c4];
            }
            __syncthreads();
            #pragma unroll
            for (int kk = 0; kk < 32; kk++) {
                int k = kc * 32 + kk;
                float a0 = os[ty * 4 + 0][k];
                float a1 = os[ty * 4 + 1][k];
                float a2 = os[ty * 4 + 2][k];
                float a3 = os[ty * 4 + 3][k];
                float4 b = *(const float4*)&Bs[kk][tx * 4];
                acc[0][0] += a0 * b.x; acc[0][1] += a0 * b.y; acc[0][2] += a0 * b.z; acc[0][3] += a0 * b.w;
                acc[1][0] += a1 * b.x; acc[1][1] += a1 * b.y; acc[1][2] += a1 * b.z; acc[1][3] += a1 * b.w;
                acc[2][0] += a2 * b.x; acc[2][1] += a2 * b.y; acc[2][2] += a2 * b.z; acc[2][3] += a2 * b.w;
                acc[3][0] += a3 * b.x; acc[3][1] += a3 * b.y; acc[3][2] += a3 * b.z; acc[3][3] += a3 * b.w;
            }
        }
        float4 bo4 = *(const float4*)(bo + nbase + tx * 4);
        #pragma unroll
        for (int rr = 0; rr < 4; rr++) {
            int p = p0 + ty * 4 + rr;
            float4 v = make_float4(acc[rr][0] + bo4.x, acc[rr][1] + bo4.y,
                                   acc[rr][2] + bo4.z, acc[rr][3] + bo4.w);
            *(float4*)(out + (size_t)p * CIN + nbase + tx * 4) = v;
        }
    }
}

extern "C" void kernel_launch(void* const* d_in, const int* in_sizes, int n_in,
                              void* d_out, int out_size) {
    (void)in_sizes; (void)n_in; (void)out_size;
    const float* x    = (const float*)d_in[0];
    const float* mask = (const float*)d_in[1];
    const float* lnw  = (const float*)d_in[2];
    const float* lnb  = (const float*)d_in[3];
    const float* wb   = (const float*)d_in[4];
    const float* wq   = (const float*)d_in[5];
    const float* wk   = (const float*)d_in[6];
    const float* wv   = (const float*)d_in[7];
    const float* wg   = (const float*)d_in[8];
    const float* bg   = (const float*)d_in[9];
    const float* wo   = (const float*)d_in[10];
    const float* bo   = (const float*)d_in[11];
    float* out = (float*)d_out;

    prep_kernel<<<260, 256>>>(wb, wq, wk, wv, wg, wo);
    lnproj_kernel<<<1024, 256>>>(x, lnw, lnb, bg);
    attn_kernel<<<1024, 256>>>(mask);
    outproj_kernel<<<1024, 256>>>(out, bo);
}

// round 3
// speedup vs baseline: 2.0768x; 2.0768x over previous
#include <cuda_runtime.h>
#include <math.h>

#define NN   256
#define CIN  128
#define HH   4
#define DD   32
#define NPOS (NN*NN)
#define FULL 0xffffffffu

// ---------------- scratch (device globals) ----------------
__device__ unsigned g_Wt[CIN][520];        // tf32 bits: [c][e]: e<128 wq*scale, <256 wk, <384 wv, <512 wg, 512..515 wb
__device__ unsigned g_Wot[CIN][CIN];       // tf32 bits: [e][c] = w_o[c][e]
__device__ float g_q[NN][HH][NN][DD];
__device__ float g_k[NN][HH][NN][DD];
__device__ float g_v[NN][HH][NN][DD];
__device__ float g_gate[(size_t)NPOS*CIN];
__device__ float g_tb[HH][NN][NN];         // [h][query q][key k]
__device__ float g_o[(size_t)NPOS*CIN];

// ---------------- helpers ----------------
__device__ __forceinline__ unsigned f2tf(float f) {
    unsigned u;
    asm("cvt.rna.tf32.f32 %0, %1;" : "=r"(u) : "f"(f));
    return u;
}
__device__ __forceinline__ void mma8(float4& d, unsigned a0, unsigned a1, unsigned a2, unsigned a3,
                                     unsigned b0, unsigned b1) {
    asm volatile("mma.sync.aligned.m16n8k8.row.col.f32.tf32.tf32.f32 "
                 "{%0,%1,%2,%3}, {%4,%5,%6,%7}, {%8,%9}, {%0,%1,%2,%3};\n"
                 : "+f"(d.x), "+f"(d.y), "+f"(d.z), "+f"(d.w)
                 : "r"(a0), "r"(a1), "r"(a2), "r"(a3), "r"(b0), "r"(b1));
}

// ---------------- weight prep ----------------
__global__ void prep_kernel(const float* __restrict__ wb, const float* __restrict__ wq,
                            const float* __restrict__ wk, const float* __restrict__ wv,
                            const float* __restrict__ wg, const float* __restrict__ wo) {
    int idx = blockIdx.x * blockDim.x + threadIdx.x;
    if (idx < CIN * 520) {
        int c = idx / 520, e = idx % 520;
        float val = 0.f;
        if      (e < 128) val = wq[e * CIN + c] * 0.17677669529663687f;   // 1/sqrt(32)
        else if (e < 256) val = wk[(e - 128) * CIN + c];
        else if (e < 384) val = wv[(e - 256) * CIN + c];
        else if (e < 512) val = wg[(e - 384) * CIN + c];
        else if (e < 516) val = wb[(e - 512) * CIN + c];
        g_Wt[c][e] = f2tf(val);
    }
    if (idx < CIN * CIN) {
        int e = idx / CIN, c = idx % CIN;
        g_Wot[e][c] = f2tf(wo[c * CIN + e]);
    }
}

// ---------------- fused LN + {q,k,v,gate} tf32-mma projection + tri-bias ----------------
struct LnSmem {
    unsigned xs[128][132];   // tf32 normalized activations, bank = (4r+c)%32
    unsigned Bs[128][72];    // weight chunk (64 cols), bank = (8k+n)%32
    float mu[128];
    float rs[128];
};

__global__ __launch_bounds__(256) void lnproj_kernel(const float* __restrict__ x,
                                                     const float* __restrict__ lnw,
                                                     const float* __restrict__ lnb,
                                                     const float* __restrict__ bg) {
    extern __shared__ char smem_raw[];
    LnSmem& S = *(LnSmem*)smem_raw;

    int t = threadIdx.x;
    int p0 = blockIdx.x * 128;
    int w = t >> 5, lane = t & 31;
    int gid = lane >> 2, tig = lane & 3;

    // LN stats: warp w handles rows 16w..16w+15
    for (int rr = 0; rr < 16; rr++) {
        int r = w * 16 + rr;
        const float* xp = x + (size_t)(p0 + r) * CIN;
        float v0 = xp[lane], v1 = xp[lane + 32], v2 = xp[lane + 64], v3 = xp[lane + 96];
        float s = v0 + v1 + v2 + v3;
        float q = v0 * v0 + v1 * v1 + v2 * v2 + v3 * v3;
        #pragma unroll
        for (int off = 16; off; off >>= 1) {
            s += __shfl_down_sync(FULL, s, off);
            q += __shfl_down_sync(FULL, q, off);
        }
        if (lane == 0) {
            float m = s * (1.f / 128.f);
            S.mu[r] = m;
            S.rs[r] = rsqrtf(q * (1.f / 128.f) - m * m + 1e-5f);
        }
    }
    __syncthreads();

    // normalize + tf32 into xs
    for (int idx = t * 4; idx < 128 * 128; idx += 1024) {
        int r = idx >> 7, c = idx & 127;
        float4 xv = *(const float4*)(x + (size_t)(p0 + r) * CIN + c);
        float4 wv = *(const float4*)(lnw + c);
        float4 bv = *(const float4*)(lnb + c);
        float m = S.mu[r], rs = S.rs[r];
        S.xs[r][c + 0] = f2tf((xv.x - m) * rs * wv.x + bv.x);
        S.xs[r][c + 1] = f2tf((xv.y - m) * rs * wv.y + bv.y);
        S.xs[r][c + 2] = f2tf((xv.z - m) * rs * wv.z + bv.z);
        S.xs[r][c + 3] = f2tf((xv.w - m) * rs * wv.w + bv.w);
    }
    __syncthreads();

    // A fragments: 16 k-tiles, register resident
    unsigned af[16][4];
    int r0 = w * 16;
    #pragma unroll
    for (int kt = 0; kt < 16; kt++) {
        af[kt][0] = S.xs[r0 + gid][kt * 8 + tig];
        af[kt][1] = S.xs[r0 + gid + 8][kt * 8 + tig];
        af[kt][2] = S.xs[r0 + gid][kt * 8 + tig + 4];
        af[kt][3] = S.xs[r0 + gid + 8][kt * 8 + tig + 4];
    }

    int p_lo = p0 + r0 + gid, p_hi = p_lo + 8;
    int ii = p_lo >> 8;                  // constant within CTA
    int jj_lo = p_lo & 255, jj_hi = p_hi & 255;

    // 8 chunks of 64 output cols
    for (int nc = 0; nc < 8; nc++) {
        __syncthreads();
        for (int idx = t; idx < 128 * 16; idx += 256) {
            int k = idx >> 4, c4 = (idx & 15) * 4;
            *(uint4*)&S.Bs[k][c4] = *(const uint4*)&g_Wt[k][nc * 64 + c4];
        }
        __syncthreads();

        float4 acc[8];
        #pragma unroll
        for (int nt = 0; nt < 8; nt++) acc[nt] = make_float4(0.f, 0.f, 0.f, 0.f);

        #pragma unroll
        for (int kt = 0; kt < 16; kt++) {
            #pragma unroll
            for (int nt = 0; nt < 8; nt++) {
                unsigned b0 = S.Bs[kt * 8 + tig][nt * 8 + gid];
                unsigned b1 = S.Bs[kt * 8 + tig + 4][nt * 8 + gid];
                mma8(acc[nt], af[kt][0], af[kt][1], af[kt][2], af[kt][3], b0, b1);
            }
        }

        int sel = nc >> 1;   // 0=q 1=k 2=v 3=gate (uniform per nc)
        #pragma unroll
        for (int nt = 0; nt < 8; nt++) {
            int e0 = nc * 64 + nt * 8 + 2 * tig;
            int loc = e0 & 127;
            int hh = loc >> 5, d0 = loc & 31;
            float2 vlo = make_float2(acc[nt].x, acc[nt].y);
            float2 vhi = make_float2(acc[nt].z, acc[nt].w);
            if (sel == 0) {
                *(float2*)&g_q[ii][hh][jj_lo][d0] = vlo;
                *(float2*)&g_q[ii][hh][jj_hi][d0] = vhi;
            } else if (sel == 1) {
                *(float2*)&g_k[ii][hh][jj_lo][d0] = vlo;
                *(float2*)&g_k[ii][hh][jj_hi][d0] = vhi;
            } else if (sel == 2) {
                *(float2*)&g_v[ii][hh][jj_lo][d0] = vlo;
                *(float2*)&g_v[ii][hh][jj_hi][d0] = vhi;
            } else {
                float2 bgv = *(const float2*)(bg + loc);
                float2 glo, ghi;
                glo.x = 1.f / (1.f + __expf(-(vlo.x + bgv.x)));
                glo.y = 1.f / (1.f + __expf(-(vlo.y + bgv.y)));
                ghi.x = 1.f / (1.f + __expf(-(vhi.x + bgv.x)));
                ghi.y = 1.f / (1.f + __expf(-(vhi.y + bgv.y)));
                *(float2*)(g_gate + (size_t)p_lo * CIN + loc) = glo;
                *(float2*)(g_gate + (size_t)p_hi * CIN + loc) = ghi;
            }
        }
    }

    // triangle bias: 512 (row, head) dots per CTA
    for (int pp = t; pp < 512; pp += 256) {
        int r = pp >> 2, hh = pp & 3;
        float acc = 0.f;
        #pragma unroll 8
        for (int c = 0; c < 128; c++)
            acc += __uint_as_float(S.xs[r][c]) * __uint_as_float(g_Wt[c][512 + hh]);
        int p = p0 + r;
        g_tb[hh][p >> 8][p & 255] = acc;   // [h][query][key]
    }
}

// ---------------- tf32-mma flash attention + gating ----------------
struct AttnSmem {
    unsigned Qs[128][36];   // bank = (4r+c)%32
    unsigned Ks[256][36];
    unsigned Vs[256][40];   // bank = (8r+c)%32
    float mbs[256];
};

__global__ __launch_bounds__(256) void attn_kernel(const float* __restrict__ mask) {
    extern __shared__ char smem_raw[];
    AttnSmem& S = *(AttnSmem*)smem_raw;

    int bid = blockIdx.x;
    int i  = bid >> 3;
    int h  = (bid >> 1) & 3;
    int qt = bid & 1;
    int t = threadIdx.x;
    int w = t >> 5, lane = t & 31;
    int gid = lane >> 2, tig = lane & 3;

    // stage Q (this 128-row tile), full K and V, mask bias
    const float* qg = &g_q[i][h][qt * 128][0];
    for (int idx = t; idx < 128 * 8; idx += 256) {
        int r = idx >> 3, c4 = (idx & 7) * 4;
        float4 v = *(const float4*)(qg + r * 32 + c4);
        S.Qs[r][c4 + 0] = f2tf(v.x); S.Qs[r][c4 + 1] = f2tf(v.y);
        S.Qs[r][c4 + 2] = f2tf(v.z); S.Qs[r][c4 + 3] = f2tf(v.w);
    }
    const float* kg = &g_k[i][h][0][0];
    const float* vg = &g_v[i][h][0][0];
    for (int idx = t; idx < 256 * 8; idx += 256) {
        int r = idx >> 3, c4 = (idx & 7) * 4;
        float4 kv = *(const float4*)(kg + r * 32 + c4);
        S.Ks[r][c4 + 0] = f2tf(kv.x); S.Ks[r][c4 + 1] = f2tf(kv.y);
        S.Ks[r][c4 + 2] = f2tf(kv.z); S.Ks[r][c4 + 3] = f2tf(kv.w);
        float4 vv = *(const float4*)(vg + r * 32 + c4);
        S.Vs[r][c4 + 0] = f2tf(vv.x); S.Vs[r][c4 + 1] = f2tf(vv.y);
        S.Vs[r][c4 + 2] = f2tf(vv.z); S.Vs[r][c4 + 3] = f2tf(vv.w);
    }
    S.mbs[t] = 1e9f * (mask[i * NN + t] - 1.0f);
    __syncthreads();

    // Q fragments
    unsigned aq[4][4];
    int r0 = w * 16;
    #pragma unroll
    for (int kt = 0; kt < 4; kt++) {
        aq[kt][0] = S.Qs[r0 + gid][kt * 8 + tig];
        aq[kt][1] = S.Qs[r0 + gid + 8][kt * 8 + tig];
        aq[kt][2] = S.Qs[r0 + gid][kt * 8 + tig + 4];
        aq[kt][3] = S.Qs[r0 + gid + 8][kt * 8 + tig + 4];
    }

    float4 oacc[4];
    #pragma unroll
    for (int n = 0; n < 4; n++) oacc[n] = make_float4(0.f, 0.f, 0.f, 0.f);
    float l_lo = 0.f, l_hi = 0.f;

    int q_lo = qt * 128 + r0 + gid, q_hi = q_lo + 8;
    const float* tb_lo = &g_tb[h][q_lo][0];
    const float* tb_hi = &g_tb[h][q_hi][0];

    int base = lane & ~3;
    int s_src = tig >> 1;
    bool odd = tig & 1;

    for (int kb = 0; kb < 4; kb++) {
        int kbase = kb * 64;

        // S = Q @ K^T for this 64-key tile
        float4 s[8];
        #pragma unroll
        for (int nt = 0; nt < 8; nt++) s[nt] = make_float4(0.f, 0.f, 0.f, 0.f);
        #pragma unroll
        for (int nt = 0; nt < 8; nt++) {
            int key = kbase + nt * 8 + gid;
            #pragma unroll
            for (int kt = 0; kt < 4; kt++) {
                unsigned b0 = S.Ks[key][kt * 8 + tig];
                unsigned b1 = S.Ks[key][kt * 8 + tig + 4];
                mma8(s[nt], aq[kt][0], aq[kt][1], aq[kt][2], aq[kt][3], b0, b1);
            }
        }

        // bias + exp (no max-shift: scores are O(1) by construction; mask -> -1e9 underflows to 0)
        float4 p[8];
        #pragma unroll
        for (int nt = 0; nt < 8; nt++) {
            int c0 = kbase + nt * 8 + 2 * tig;
            float2 tl = *(const float2*)(tb_lo + c0);
            float2 th = *(const float2*)(tb_hi + c0);
            float m0 = S.mbs[c0], m1 = S.mbs[c0 + 1];
            p[nt].x = __expf(s[nt].x + tl.x + m0);
            p[nt].y = __expf(s[nt].y + tl.y + m1);
            p[nt].z = __expf(s[nt].z + th.x + m0);
            p[nt].w = __expf(s[nt].w + th.y + m1);
            l_lo += p[nt].x + p[nt].y;
            l_hi += p[nt].z + p[nt].w;
        }

        // O += P @ V  (C-frag -> A-frag via intra-group shuffles)
        #pragma unroll
        for (int kt = 0; kt < 8; kt++) {
            float v0 = __shfl_sync(FULL, p[kt].x, base + s_src);
            float v1 = __shfl_sync(FULL, p[kt].y, base + s_src);
            float v2 = __shfl_sync(FULL, p[kt].z, base + s_src);
            float v3 = __shfl_sync(FULL, p[kt].w, base + s_src);
            float w0 = __shfl_sync(FULL, p[kt].x, base + s_src + 2);
            float w1 = __shfl_sync(FULL, p[kt].y, base + s_src + 2);
            float w2 = __shfl_sync(FULL, p[kt].z, base + s_src + 2);
            float w3 = __shfl_sync(FULL, p[kt].w, base + s_src + 2);
            unsigned a0 = f2tf(odd ? v1 : v0);
            unsigned a1 = f2tf(odd ? v3 : v2);
            unsigned a2 = f2tf(odd ? w1 : w0);
            unsigned a3 = f2tf(odd ? w3 : w2);
            int krow = kbase + kt * 8;
            #pragma unroll
            for (int ntd = 0; ntd < 4; ntd++) {
                unsigned b0 = S.Vs[krow + tig][ntd * 8 + gid];
                unsigned b1 = S.Vs[krow + tig + 4][ntd * 8 + gid];
                mma8(oacc[ntd], a0, a1, a2, a3, b0, b1);
            }
        }
    }

    // finalize softmax denominator across the 4-lane row group
    l_lo += __shfl_xor_sync(FULL, l_lo, 1);
    l_lo += __shfl_xor_sync(FULL, l_lo, 2);
    l_hi += __shfl_xor_sync(FULL, l_hi, 1);
    l_hi += __shfl_xor_sync(FULL, l_hi, 2);
    float inv_lo = 1.f / l_lo, inv_hi = 1.f / l_hi;

    // gated store
    size_t base_lo = ((size_t)(i * NN + q_lo)) * CIN + h * DD;
    size_t base_hi = ((size_t)(i * NN + q_hi)) * CIN + h * DD;
    #pragma unroll
    for (int ntd = 0; ntd < 4; ntd++) {
        int d0 = ntd * 8 + 2 * tig;
        float2 glo = *(const float2*)(g_gate + base_lo + d0);
        float2 ghi = *(const float2*)(g_gate + base_hi + d0);
        float2 olo = make_float2(oacc[ntd].x * inv_lo * glo.x, oacc[ntd].y * inv_lo * glo.y);
        float2 ohi = make_float2(oacc[ntd].z * inv_hi * ghi.x, oacc[ntd].w * inv_hi * ghi.y);
        *(float2*)(g_o + base_lo + d0) = olo;
        *(float2*)(g_o + base_hi + d0) = ohi;
    }
}

// ---------------- tf32-mma output projection ----------------
struct OutSmem {
    unsigned os[128][132];
    unsigned Bs[128][136];   // bank = (8k+n)%32
};

__global__ __launch_bounds__(256) void outproj_kernel(float* __restrict__ out,
                                                      const float* __restrict__ bo) {
    extern __shared__ char smem_raw[];
    OutSmem& S = *(OutSmem*)smem_raw;

    int t = threadIdx.x;
    int p0 = blockIdx.x * 128;
    int w = t >> 5, lane = t & 31;
    int gid = lane >> 2, tig = lane & 3;

    for (int idx = t * 4; idx < 128 * 128; idx += 1024) {
        int r = idx >> 7, c = idx & 127;
        float4 v = *(const float4*)(g_o + (size_t)(p0 + r) * CIN + c);
        S.os[r][c + 0] = f2tf(v.x); S.os[r][c + 1] = f2tf(v.y);
        S.os[r][c + 2] = f2tf(v.z); S.os[r][c + 3] = f2tf(v.w);
    }
    for (int idx = t; idx < 128 * 32; idx += 256) {
        int k = idx >> 5, c4 = (idx & 31) * 4;
        *(uint4*)&S.Bs[k][c4] = *(const uint4*)&g_Wot[k][c4];
    }
    __syncthreads();

    unsigned af[16][4];
    int r0 = w * 16;
    #pragma unroll
    for (int kt = 0; kt < 16; kt++) {
        af[kt][0] = S.os[r0 + gid][kt * 8 + tig];
        af[kt][1] = S.os[r0 + gid + 8][kt * 8 + tig];
        af[kt][2] = S.os[r0 + gid][kt * 8 + tig + 4];
        af[kt][3] = S.os[r0 + gid + 8][kt * 8 + tig + 4];
    }

    float4 acc[16];
    #pragma unroll
    for (int nt = 0; nt < 16; nt++) acc[nt] = make_float4(0.f, 0.f, 0.f, 0.f);

    #pragma unroll
    for (int kt = 0; kt < 16; kt++) {
        #pragma unroll
        for (int nt = 0; nt < 16; nt++) {
            unsigned b0 = S.Bs[kt * 8 + tig][nt * 8 + gid];
            unsigned b1 = S.Bs[kt * 8 + tig + 4][nt * 8 + gid];
            mma8(acc[nt], af[kt][0], af[kt][1], af[kt][2], af[kt][3], b0, b1);
        }
    }

    int p_lo = p0 + r0 + gid, p_hi = p_lo + 8;
    #pragma unroll
    for (int nt = 0; nt < 16; nt++) {
        int c0 = nt * 8 + 2 * tig;
        float2 bo2 = *(const float2*)(bo + c0);
        *(float2*)(out + (size_t)p_lo * CIN + c0) =
            make_float2(acc[nt].x + bo2.x, acc[nt].y + bo2.y);
        *(float2*)(out + (size_t)p_hi * CIN + c0) =
            make_float2(acc[nt].z + bo2.x, acc[nt].w + bo2.y);
    }
}

extern "C" void kernel_launch(void* const* d_in, const int* in_sizes, int n_in,
                              void* d_out, int out_size) {
    (void)in_sizes; (void)n_in; (void)out_size;
    const float* x    = (const float*)d_in[0];
    const float* mask = (const float*)d_in[1];
    const float* lnw  = (const float*)d_in[2];
    const float* lnb  = (const float*)d_in[3];
    const float* wb   = (const float*)d_in[4];
    const float* wq   = (const float*)d_in[5];
    const float* wk   = (const float*)d_in[6];
    const float* wv   = (const float*)d_in[7];
    const float* wg   = (const float*)d_in[8];
    const float* bg   = (const float*)d_in[9];
    const float* wo   = (const float*)d_in[10];
    const float* bo   = (const float*)d_in[11];
    float* out = (float*)d_out;

    cudaFuncSetAttribute(lnproj_kernel,  cudaFuncAttributeMaxDynamicSharedMemorySize, (int)sizeof(LnSmem));
    cudaFuncSetAttribute(attn_kernel,    cudaFuncAttributeMaxDynamicSharedMemorySize, (int)sizeof(AttnSmem));
    cudaFuncSetAttribute(outproj_kernel, cudaFuncAttributeMaxDynamicSharedMemorySize, (int)sizeof(OutSmem));

    prep_kernel<<<260, 256>>>(wb, wq, wk, wv, wg, wo);
    lnproj_kernel<<<512, 256, sizeof(LnSmem)>>>(x, lnw, lnb, bg);
    attn_kernel<<<2048, 256, sizeof(AttnSmem)>>>(mask);
    outproj_kernel<<<512, 256, sizeof(OutSmem)>>>(out, bo);
}

// round 6
// speedup vs baseline: 3.5236x; 1.6966x over previous
#include <cuda_runtime.h>
#include <cuda_fp16.h>
#include <math.h>

#define NN   256
#define CIN  128
#define HH   4
#define DD   32
#define NPOS (NN*NN)
#define FULL 0xffffffffu

// ---------------- scratch (device globals) ----------------
__device__ __half g_Wh[CIN][512];          // [c][e] fp16: e<128 wq*scale, <256 wk, <384 wv, <512 wg
__device__ float  g_wbt[HH][CIN];          // tri-bias weights f32
__device__ __half g_Woh[CIN][CIN];         // [e][c] = w_o[c][e] fp16
__device__ __half g_q[NN][HH][NN][DD];
__device__ __half g_k[NN][HH][NN][DD];
__device__ __half g_v[NN][HH][NN][DD];
__device__ __half g_gate[(size_t)NPOS*CIN];
__device__ float  g_tb[HH][NN][NN];        // [h][query][key]
__device__ __half g_o[(size_t)NPOS*CIN];

// ---------------- helpers ----------------
__device__ __forceinline__ unsigned cvta_s(const void* p) {
    return (unsigned)__cvta_generic_to_shared(p);
}
__device__ __forceinline__ void ldsm4(uint4& d, unsigned a) {
    asm volatile("ldmatrix.sync.aligned.m8n8.x4.shared.b16 {%0,%1,%2,%3}, [%4];"
                 : "=r"(d.x), "=r"(d.y), "=r"(d.z), "=r"(d.w) : "r"(a));
}
__device__ __forceinline__ void ldsm4t(uint4& d, unsigned a) {
    asm volatile("ldmatrix.sync.aligned.m8n8.x4.trans.shared.b16 {%0,%1,%2,%3}, [%4];"
                 : "=r"(d.x), "=r"(d.y), "=r"(d.z), "=r"(d.w) : "r"(a));
}
__device__ __forceinline__ void mma16(float4& d, unsigned a0, unsigned a1, unsigned a2, unsigned a3,
                                      unsigned b0, unsigned b1) {
    asm volatile("mma.sync.aligned.m16n8k16.row.col.f32.f16.f16.f32 "
                 "{%0,%1,%2,%3},{%4,%5,%6,%7},{%8,%9},{%0,%1,%2,%3};"
                 : "+f"(d.x), "+f"(d.y), "+f"(d.z), "+f"(d.w)
                 : "r"(a0), "r"(a1), "r"(a2), "r"(a3), "r"(b0), "r"(b1));
}
__device__ __forceinline__ unsigned packh2(float lo, float hi) {
    unsigned r;
    asm("cvt.rn.f16x2.f32 %0, %1, %2;" : "=r"(r) : "f"(hi), "f"(lo));
    return r;
}

// ---------------- weight prep ----------------
__global__ void prep_kernel(const float* __restrict__ wb, const float* __restrict__ wq,
                            const float* __restrict__ wk, const float* __restrict__ wv,
                            const float* __restrict__ wg, const float* __restrict__ wo) {
    int idx = blockIdx.x * blockDim.x + threadIdx.x;
    if (idx < CIN * 512) {
        int c = idx >> 9, e = idx & 511;
        float val;
        if      (e < 128) val = wq[e * CIN + c] * 0.17677669529663687f;   // 1/sqrt(32)
        else if (e < 256) val = wk[(e - 128) * CIN + c];
        else if (e < 384) val = wv[(e - 256) * CIN + c];
        else              val = wg[(e - 384) * CIN + c];
        g_Wh[c][e] = __float2half(val);
    }
    if (idx < HH * CIN) {
        int h = idx >> 7, c = idx & 127;
        g_wbt[h][c] = wb[h * CIN + c];
    }
    if (idx < CIN * CIN) {
        int e = idx >> 7, c = idx & 127;
        g_Woh[e][c] = __float2half(wo[c * CIN + e]);
    }
}

// ---------------- fused LN + {q,k,v,gate} fp16-mma projection + tri-bias ----------------
struct LnSmem {
    __half xs[128][136];       // 128 data cols + 8 pad (row 272B = 16 mod 128 -> ldsm conflict-free)
    __half Bs[2][128][72];     // double-buffered 64-col weight chunks (row 144B)
    float mu[128], rs[128];
};

__global__ __launch_bounds__(256) void lnproj_kernel(const float* __restrict__ x,
                                                     const float* __restrict__ lnw,
                                                     const float* __restrict__ lnb,
                                                     const float* __restrict__ bg) {
    extern __shared__ char sraw[];
    LnSmem& S = *(LnSmem*)sraw;

    int t = threadIdx.x;
    int p0 = blockIdx.x * 128;
    int w = t >> 5, lane = t & 31;
    int gid = lane >> 2, tig = lane & 3;

    // LN stats
    for (int rr = 0; rr < 16; rr++) {
        int r = w * 16 + rr;
        const float* xp = x + (size_t)(p0 + r) * CIN;
        float v0 = xp[lane], v1 = xp[lane + 32], v2 = xp[lane + 64], v3 = xp[lane + 96];
        float s = v0 + v1 + v2 + v3;
        float q = v0 * v0 + v1 * v1 + v2 * v2 + v3 * v3;
        #pragma unroll
        for (int off = 16; off; off >>= 1) {
            s += __shfl_down_sync(FULL, s, off);
            q += __shfl_down_sync(FULL, q, off);
        }
        if (lane == 0) {
            float m = s * (1.f / 128.f);
            S.mu[r] = m;
            S.rs[r] = rsqrtf(q * (1.f / 128.f) - m * m + 1e-5f);
        }
    }
    __syncthreads();

    // normalize -> fp16 xs
    for (int idx = t * 4; idx < 128 * 128; idx += 1024) {
        int r = idx >> 7, c = idx & 127;
        float4 xv = *(const float4*)(x + (size_t)(p0 + r) * CIN + c);
        float4 wv = *(const float4*)(lnw + c);
        float4 bv = *(const float4*)(lnb + c);
        float m = S.mu[r], rs = S.rs[r];
        *(__half2*)&S.xs[r][c]     = __floats2half2_rn((xv.x - m) * rs * wv.x + bv.x,
                                                       (xv.y - m) * rs * wv.y + bv.y);
        *(__half2*)&S.xs[r][c + 2] = __floats2half2_rn((xv.z - m) * rs * wv.z + bv.z,
                                                       (xv.w - m) * rs * wv.w + bv.w);
    }
    // preload weight chunk 0
    for (int f = t; f < 1024; f += 256) {
        int k = f >> 3, c8 = (f & 7) * 8;
        *(uint4*)&S.Bs[0][k][c8] = *(const uint4*)&g_Wh[k][c8];
    }
    __syncthreads();

    int wm = w >> 1, wn = w & 1;              // warp tile: 32 rows x 32 cols of 64-chunk
    int m8 = lane >> 3, r8 = lane & 7;

    unsigned aBase = cvta_s(&S.xs[wm * 32 + (m8 & 1) * 8 + r8][(m8 >> 1) * 8]);
    unsigned bBase[2];
    bBase[0] = cvta_s(&S.Bs[0][(m8 & 1) * 8 + r8][wn * 32 + (m8 >> 1) * 8]);
    bBase[1] = cvta_s(&S.Bs[1][(m8 & 1) * 8 + r8][wn * 32 + (m8 >> 1) * 8]);

    int p_lo0 = p0 + wm * 32 + gid;
    int ii = p_lo0 >> 8;

    for (int nc = 0; nc < 8; nc++) {
        int cur = nc & 1;
        uint4 pre[4];
        if (nc < 7) {
            #pragma unroll
            for (int j = 0; j < 4; j++) {
                int f = t + j * 256;
                int k = f >> 3, c8 = (f & 7) * 8;
                pre[j] = *(const uint4*)&g_Wh[k][(nc + 1) * 64 + c8];
            }
        }

        float4 acc[2][4];
        #pragma unroll
        for (int mt = 0; mt < 2; mt++)
            #pragma unroll
            for (int nt = 0; nt < 4; nt++) acc[mt][nt] = make_float4(0.f, 0.f, 0.f, 0.f);

        unsigned bb = bBase[cur];
        #pragma unroll
        for (int ks = 0; ks < 8; ks++) {
            uint4 A0, A1, B0, B1;
            ldsm4(A0, aBase + ks * 32);            // k-step: +16 halves along row
            ldsm4(A1, aBase + ks * 32 + 4352);     // +16 rows (16*272B)
            ldsm4t(B0, bb + ks * 2304);            // +16 k-rows (16*144B)
            ldsm4t(B1, bb + ks * 2304 + 32);       // +16 n-cols
            mma16(acc[0][0], A0.x, A0.y, A0.z, A0.w, B0.x, B0.y);
            mma16(acc[0][1], A0.x, A0.y, A0.z, A0.w, B0.z, B0.w);
            mma16(acc[0][2], A0.x, A0.y, A0.z, A0.w, B1.x, B1.y);
            mma16(acc[0][3], A0.x, A0.y, A0.z, A0.w, B1.z, B1.w);
            mma16(acc[1][0], A1.x, A1.y, A1.z, A1.w, B0.x, B0.y);
            mma16(acc[1][1], A1.x, A1.y, A1.z, A1.w, B0.z, B0.w);
            mma16(acc[1][2], A1.x, A1.y, A1.z, A1.w, B1.x, B1.y);
            mma16(acc[1][3], A1.x, A1.y, A1.z, A1.w, B1.z, B1.w);
        }

        // epilogue to gmem
        int sel = nc >> 1;   // 0=q 1=k 2=v 3=gate
        #pragma unroll
        for (int mt = 0; mt < 2; mt++) {
            int p_lo = p_lo0 + mt * 16;
            int jj_lo = p_lo & 255, jj_hi = jj_lo + 8;
            #pragma unroll
            for (int nt = 0; nt < 4; nt++) {
                int e0 = nc * 64 + wn * 32 + nt * 8 + 2 * tig;
                int loc = e0 & 127;
                int hh = loc >> 5, d0 = loc & 31;
                float4 a = acc[mt][nt];
                if (sel == 0) {
                    *(__half2*)&g_q[ii][hh][jj_lo][d0] = __floats2half2_rn(a.x, a.y);
                    *(__half2*)&g_q[ii][hh][jj_hi][d0] = __floats2half2_rn(a.z, a.w);
                } else if (sel == 1) {
                    *(__half2*)&g_k[ii][hh][jj_lo][d0] = __floats2half2_rn(a.x, a.y);
                    *(__half2*)&g_k[ii][hh][jj_hi][d0] = __floats2half2_rn(a.z, a.w);
                } else if (sel == 2) {
                    *(__half2*)&g_v[ii][hh][jj_lo][d0] = __floats2half2_rn(a.x, a.y);
                    *(__half2*)&g_v[ii][hh][jj_hi][d0] = __floats2half2_rn(a.z, a.w);
                } else {
                    float2 bg2 = *(const float2*)(bg + loc);
                    float glx = 1.f / (1.f + __expf(-(a.x + bg2.x)));
                    float gly = 1.f / (1.f + __expf(-(a.y + bg2.y)));
                    float ghx = 1.f / (1.f + __expf(-(a.z + bg2.x)));
                    float ghy = 1.f / (1.f + __expf(-(a.w + bg2.y)));
                    *(__half2*)(g_gate + (size_t)p_lo * CIN + loc) = __floats2half2_rn(glx, gly);
                    *(__half2*)(g_gate + ((size_t)p_lo + 8) * CIN + loc) = __floats2half2_rn(ghx, ghy);
                }
            }
        }

        __syncthreads();
        if (nc < 7) {
            #pragma unroll
            for (int j = 0; j < 4; j++) {
                int f = t + j * 256;
                int k = f >> 3, c8 = (f & 7) * 8;
                *(uint4*)&S.Bs[cur ^ 1][k][c8] = pre[j];
            }
        }
        __syncthreads();
    }

    // triangle bias
    for (int pp = t; pp < 512; pp += 256) {
        int rr = pp >> 2, hh = pp & 3;
        const float* wv = g_wbt[hh];
        float a = 0.f;
        #pragma unroll 16
        for (int c = 0; c < 128; c += 2) {
            float2 fx = __half22float2(*(__half2*)&S.xs[rr][c]);
            a += fx.x * wv[c] + fx.y * wv[c + 1];
        }
        int p = p0 + rr;
        g_tb[hh][p >> 8][p & 255] = a;
    }
}

// ---------------- fp16-mma flash attention + gating ----------------
struct AttnSmem {
    __half Qs[128][40];
    __half Ks[256][40];
    __half Vs[256][40];
    float mbs[256];
};

__global__ __launch_bounds__(256) void attn_kernel(const float* __restrict__ mask) {
    extern __shared__ char sraw[];
    AttnSmem& S = *(AttnSmem*)sraw;

    int bid = blockIdx.x;
    int i = bid >> 3;
    int h = (bid >> 1) & 3;
    int qt = bid & 1;
    int t = threadIdx.x;
    int w = t >> 5, lane = t & 31;
    int gid = lane >> 2, tig = lane & 3;

    const __half* qg = &g_q[i][h][qt * 128][0];
    for (int f = t; f < 512; f += 256) {
        int r = f >> 2, c8 = (f & 3) * 8;
        *(uint4*)&S.Qs[r][c8] = *(const uint4*)(qg + r * 32 + c8);
    }
    const __half* kg = &g_k[i][h][0][0];
    const __half* vg = &g_v[i][h][0][0];
    for (int f = t; f < 1024; f += 256) {
        int r = f >> 2, c8 = (f & 3) * 8;
        *(uint4*)&S.Ks[r][c8] = *(const uint4*)(kg + r * 32 + c8);
        *(uint4*)&S.Vs[r][c8] = *(const uint4*)(vg + r * 32 + c8);
    }
    S.mbs[t] = 1e9f * (mask[i * NN + t] - 1.0f);
    __syncthreads();

    int m8 = lane >> 3, r8 = lane & 7;

    // Q fragments (resident): rows w*16..w*16+15, d=32 -> 2 ksteps
    unsigned qA = cvta_s(&S.Qs[w * 16 + (m8 & 1) * 8 + r8][(m8 >> 1) * 8]);
    uint4 aq0, aq1;
    ldsm4(aq0, qA);
    ldsm4(aq1, qA + 32);

    unsigned kA = cvta_s(&S.Ks[(m8 & 1) * 8 + r8][(m8 >> 1) * 8]);
    unsigned vA = cvta_s(&S.Vs[(m8 & 1) * 8 + r8][(m8 >> 1) * 8]);

    float4 oacc[4];
    #pragma unroll
    for (int n = 0; n < 4; n++) oacc[n] = make_float4(0.f, 0.f, 0.f, 0.f);
    float l_lo = 0.f, l_hi = 0.f;

    int q_lo = qt * 128 + w * 16 + gid, q_hi = q_lo + 8;
    const float* tb_lo = &g_tb[h][q_lo][0];
    const float* tb_hi = &g_tb[h][q_hi][0];

    for (int kb = 0; kb < 4; kb++) {
        int kbase = kb * 64;

        // S = Q @ K^T   (K stored [key][d] is already col-major kxn -> NON-trans ldsm)
        float4 s[8];
        #pragma unroll
        for (int nt = 0; nt < 8; nt++) s[nt] = make_float4(0.f, 0.f, 0.f, 0.f);
        #pragma unroll
        for (int ntp = 0; ntp < 4; ntp++) {
            unsigned ka = kA + (kbase + ntp * 16) * 80;
            uint4 B0, B1;
            ldsm4(B0, ka);        // {(key0-7,d0-7),(key8-15,d0-7),(key0-7,d8-15),(key8-15,d8-15)}
            ldsm4(B1, ka + 32);   // d16-31
            mma16(s[2 * ntp],     aq0.x, aq0.y, aq0.z, aq0.w, B0.x, B0.z);
            mma16(s[2 * ntp],     aq1.x, aq1.y, aq1.z, aq1.w, B1.x, B1.z);
            mma16(s[2 * ntp + 1], aq0.x, aq0.y, aq0.z, aq0.w, B0.y, B0.w);
            mma16(s[2 * ntp + 1], aq1.x, aq1.y, aq1.z, aq1.w, B1.y, B1.w);
        }

        // bias + exp + pack to fp16 A-fragments (register-only C->A)
        unsigned pa[4][4];
        #pragma unroll
        for (int nt = 0; nt < 8; nt++) {
            int c0 = kbase + nt * 8 + 2 * tig;
            float2 tl = *(const float2*)(tb_lo + c0);
            float2 th = *(const float2*)(tb_hi + c0);
            float mb0 = S.mbs[c0], mb1 = S.mbs[c0 + 1];
            float px = __expf(s[nt].x + tl.x + mb0);
            float py = __expf(s[nt].y + tl.y + mb1);
            float pz = __expf(s[nt].z + th.x + mb0);
            float pw = __expf(s[nt].w + th.y + mb1);
            l_lo += px + py;
            l_hi += pz + pw;
            int ktp = nt >> 1;
            if (!(nt & 1)) {
                pa[ktp][0] = packh2(px, py);
                pa[ktp][1] = packh2(pz, pw);
            } else {
                pa[ktp][2] = packh2(px, py);
                pa[ktp][3] = packh2(pz, pw);
            }
        }

        // O += P @ V   (V stored [key][d] = row-major kxn -> trans ldsm)
        #pragma unroll
        for (int ktp = 0; ktp < 4; ktp++) {
            unsigned va = vA + (kbase + ktp * 16) * 80;
            uint4 V0, V1;
            ldsm4t(V0, va);        // {b0 d0-7, b1 d0-7, b0 d8-15, b1 d8-15}
            ldsm4t(V1, va + 32);   // d16-31
            mma16(oacc[0], pa[ktp][0], pa[ktp][1], pa[ktp][2], pa[ktp][3], V0.x, V0.y);
            mma16(oacc[1], pa[ktp][0], pa[ktp][1], pa[ktp][2], pa[ktp][3], V0.z, V0.w);
            mma16(oacc[2], pa[ktp][0], pa[ktp][1], pa[ktp][2], pa[ktp][3], V1.x, V1.y);
            mma16(oacc[3], pa[ktp][0], pa[ktp][1], pa[ktp][2], pa[ktp][3], V1.z, V1.w);
        }
    }

    l_lo += __shfl_xor_sync(FULL, l_lo, 1);
    l_lo += __shfl_xor_sync(FULL, l_lo, 2);
    l_hi += __shfl_xor_sync(FULL, l_hi, 1);
    l_hi += __shfl_xor_sync(FULL, l_hi, 2);
    float inv_lo = 1.f / l_lo, inv_hi = 1.f / l_hi;

    size_t base_lo = ((size_t)(i * NN + q_lo)) * CIN + h * DD;
    size_t base_hi = ((size_t)(i * NN + q_hi)) * CIN + h * DD;
    #pragma unroll
    for (int ntd = 0; ntd < 4; ntd++) {
        int d0 = ntd * 8 + 2 * tig;
        float2 gl = __half22float2(*(__half2*)(g_gate + base_lo + d0));
        float2 gh = __half22float2(*(__half2*)(g_gate + base_hi + d0));
        *(__half2*)(g_o + base_lo + d0) =
            __floats2half2_rn(oacc[ntd].x * inv_lo * gl.x, oacc[ntd].y * inv_lo * gl.y);
        *(__half2*)(g_o + base_hi + d0) =
            __floats2half2_rn(oacc[ntd].z * inv_hi * gh.x, oacc[ntd].w * inv_hi * gh.y);
    }
}

// ---------------- fp16-mma output projection ----------------
struct OutSmem {
    __half os[128][136];    // 128 data cols + 8 pad
    __half Ws[128][136];
};

__global__ __launch_bounds__(256) void outproj_kernel(float* __restrict__ out,
                                                      const float* __restrict__ bo) {
    extern __shared__ char sraw[];
    OutSmem& S = *(OutSmem*)sraw;

    int t = threadIdx.x;
    int p0 = blockIdx.x * 128;
    int w = t >> 5, lane = t & 31;
    int gid = lane >> 2, tig = lane & 3;

    for (int f = t; f < 2048; f += 256) {
        int r = f >> 4, c8 = (f & 15) * 8;
        *(uint4*)&S.os[r][c8] = *(const uint4*)(g_o + (size_t)(p0 + r) * CIN + c8);
        *(uint4*)&S.Ws[r][c8] = *(const uint4*)&g_Woh[r][c8];
    }
    __syncthreads();

    int wm = w >> 1, wn = w & 1;           // warp tile 32 rows x 64 cols
    int m8 = lane >> 3, r8 = lane & 7;

    unsigned aBase = cvta_s(&S.os[wm * 32 + (m8 & 1) * 8 + r8][(m8 >> 1) * 8]);
    unsigned bBase = cvta_s(&S.Ws[(m8 & 1) * 8 + r8][wn * 64 + (m8 >> 1) * 8]);

    float4 acc[2][8];
    #pragma unroll
    for (int mt = 0; mt < 2; mt++)
        #pragma unroll
        for (int nt = 0; nt < 8; nt++) acc[mt][nt] = make_float4(0.f, 0.f, 0.f, 0.f);

    #pragma unroll
    for (int ks = 0; ks < 8; ks++) {
        uint4 A0, A1;
        ldsm4(A0, aBase + ks * 32);
        ldsm4(A1, aBase + ks * 32 + 4352);   // +16 rows (16*272B)
        uint4 B[4];
        #pragma unroll
        for (int ngp = 0; ngp < 4; ngp++) ldsm4t(B[ngp], bBase + ks * 4352 + ngp * 32);
        #pragma unroll
        for (int ngp = 0; ngp < 4; ngp++) {
            mma16(acc[0][2 * ngp],     A0.x, A0.y, A0.z, A0.w, B[ngp].x, B[ngp].y);
            mma16(acc[0][2 * ngp + 1], A0.x, A0.y, A0.z, A0.w, B[ngp].z, B[ngp].w);
            mma16(acc[1][2 * ngp],     A1.x, A1.y, A1.z, A1.w, B[ngp].x, B[ngp].y);
            mma16(acc[1][2 * ngp + 1], A1.x, A1.y, A1.z, A1.w, B[ngp].z, B[ngp].w);
        }
    }

    #pragma unroll
    for (int mt = 0; mt < 2; mt++) {
        int p_lo = p0 + wm * 32 + mt * 16 + gid;
        int p_hi = p_lo + 8;
        #pragma unroll
        for (int nt = 0; nt < 8; nt++) {
            int c0 = wn * 64 + nt * 8 + 2 * tig;
            float2 bo2 = *(const float2*)(bo + c0);
            *(float2*)(out + (size_t)p_lo * CIN + c0) =
                make_float2(acc[mt][nt].x + bo2.x, acc[mt][nt].y + bo2.y);
            *(float2*)(out + (size_t)p_hi * CIN + c0) =
                make_float2(acc[mt][nt].z + bo2.x, acc[mt][nt].w + bo2.y);
        }
    }
}

extern "C" void kernel_launch(void* const* d_in, const int* in_sizes, int n_in,
                              void* d_out, int out_size) {
    (void)in_sizes; (void)n_in; (void)out_size;
    const float* x    = (const float*)d_in[0];
    const float* mask = (const float*)d_in[1];
    const float* lnw  = (const float*)d_in[2];
    const float* lnb  = (const float*)d_in[3];
    const float* wb   = (const float*)d_in[4];
    const float* wq   = (const float*)d_in[5];
    const float* wk   = (const float*)d_in[6];
    const float* wv   = (const float*)d_in[7];
    const float* wg   = (const float*)d_in[8];
    const float* bg   = (const float*)d_in[9];
    const float* wo   = (const float*)d_in[10];
    const float* bo   = (const float*)d_in[11];
    float* out = (float*)d_out;

    cudaFuncSetAttribute(lnproj_kernel,  cudaFuncAttributeMaxDynamicSharedMemorySize, (int)sizeof(LnSmem));
    cudaFuncSetAttribute(attn_kernel,    cudaFuncAttributeMaxDynamicSharedMemorySize, (int)sizeof(AttnSmem));
    cudaFuncSetAttribute(outproj_kernel, cudaFuncAttributeMaxDynamicSharedMemorySize, (int)sizeof(OutSmem));

    prep_kernel<<<256, 256>>>(wb, wq, wk, wv, wg, wo);
    lnproj_kernel<<<512, 256, sizeof(LnSmem)>>>(x, lnw, lnb, bg);
    attn_kernel<<<2048, 256, sizeof(AttnSmem)>>>(mask);
    outproj_kernel<<<512, 256, sizeof(OutSmem)>>>(out, bo);
}